// round 8
// baseline (speedup 1.0000x reference)
#include <cuda_runtime.h>
#include <cstdint>

// ---------------- Fused single-kernel: M-compute prologue + warp-private
// TMA-pipelined streaming GEMV.
// out[t,k] = sum_a x[t,a] * M[k,a],
// M[k,a]   = sum_ij ( P_re[i,j] A_real[k,i,j,a] - P_im[i,j] A_imag[k,i,j,a] )
#define WARPS_PB   8
#define BLOCK_T    256
#define ROWS_W     32                          // rows per warp-stage chunk
#define F4_W       (ROWS_W * 25)               // 800 float4 per stage
#define STAGES     2
#define SMEM_BYTES (WARPS_PB * STAGES * F4_W * 16)   // 204800 B -> 1 block/SM

__device__ __forceinline__ void mbar_wait(unsigned mbar, unsigned phase) {
    unsigned done;
    asm volatile("{\n\t.reg .pred p;\n\t"
                 "mbarrier.try_wait.parity.acquire.cta.shared::cta.b64 p, [%1], %2;\n\t"
                 "selp.b32 %0, 1, 0, p;\n\t}"
                 : "=r"(done) : "r"(mbar), "r"(phase) : "memory");
    while (!done) {
        asm volatile("{\n\t.reg .pred p;\n\t"
                     "mbarrier.try_wait.parity.acquire.cta.shared::cta.b64 p, [%1], %2, 0x989680;\n\t"
                     "selp.b32 %0, 1, 0, p;\n\t}"
                     : "=r"(done) : "r"(mbar), "r"(phase) : "memory");
    }
}

__global__ void __launch_bounds__(BLOCK_T, 1) fused_kernel(
    const float* __restrict__ x,
    const float* __restrict__ A_real,
    const float* __restrict__ A_imag,
    const float* __restrict__ psi_real,
    const float* __restrict__ psi_imag,
    float2* __restrict__ out,
    int batch, int nchunks)
{
    extern __shared__ __align__(128) float4 sx[];   // [WARPS_PB][STAGES][F4_W]
    __shared__ __align__(16) float sMf[200];
    __shared__ __align__(8) unsigned long long mbar_store[WARPS_PB * STAGES];

    int tid  = threadIdx.x;
    int wid  = tid >> 5;
    int lane = tid & 31;

    unsigned mbar_base = (unsigned)__cvta_generic_to_shared(&mbar_store[0]);
    unsigned wmbar = mbar_base + (wid * STAGES) * 8;
    float4* ws = sx + (size_t)wid * (STAGES * F4_W);

    if (tid < WARPS_PB * STAGES)
        asm volatile("mbarrier.init.shared.b64 [%0], %1;"
                     :: "r"(mbar_base + tid * 8), "r"(1) : "memory");
    __syncthreads();

    int gwarp  = blockIdx.x * WARPS_PB + wid;
    int stride = gridDim.x * WARPS_PB;

    // Issue one 32-row chunk into warp-stage s (single bulk copy, lane 0).
    auto issue = [&](int chunk, int s) {
        if (lane == 0) {
            int rows = batch - chunk * ROWS_W;
            if (rows > ROWS_W) rows = ROWS_W;
            unsigned bytes = (unsigned)rows * 400u;
            unsigned mb = wmbar + s * 8;
            asm volatile("mbarrier.arrive.expect_tx.shared.b64 _, [%0], %1;"
                         :: "r"(mb), "r"(bytes) : "memory");
            unsigned dst = (unsigned)__cvta_generic_to_shared(ws + s * F4_W);
            const float* src = x + (size_t)chunk * (ROWS_W * 100);
            asm volatile("cp.async.bulk.shared::cta.global.mbarrier::complete_tx::bytes "
                         "[%0], [%1], %2, [%3];"
                         :: "r"(dst), "l"(src), "r"(bytes), "r"(mb) : "memory");
        }
    };

    // Prologue: enqueue both stages of every warp first, so the copy engines
    // are streaming while we compute M below.
    if (gwarp < nchunks)          issue(gwarp, 0);
    if (gwarp + stride < nchunks) issue(gwarp + stride, 1);

    // Fused stage 1 (R4-proven shape): tid<200 computes one (k,a) entry,
    // hidden under the first chunks' flight. A is L2-hot across blocks.
    if (tid < 200) {
        int k = tid / 100, a = tid - k * 100;
        float pr[10], pi[10];
        #pragma unroll
        for (int q = 0; q < 10; q++) { pr[q] = psi_real[q]; pi[q] = psi_imag[q]; }
        float acc = 0.0f;
        #pragma unroll
        for (int i = 0; i < 10; i++) {
            #pragma unroll
            for (int j = 0; j < 10; j++) {
                float Pre = pr[i] * pr[j] + pi[i] * pi[j];
                float Pim = pr[i] * pi[j] - pi[i] * pr[j];
                int idx = ((k * 10 + i) * 10 + j) * 100 + a;
                acc = fmaf(Pre,  __ldg(A_real + idx), acc);
                acc = fmaf(-Pim, __ldg(A_imag + idx), acc);
            }
        }
        sMf[tid] = acc;
    }
    __syncthreads();
    const float4* sM4 = reinterpret_cast<const float4*>(sMf);   // [50]

    // Steady loop: warp-private, no block barriers.
    int cnt = 0;
    for (int c = gwarp; c < nchunks; c += stride, cnt++) {
        int s = cnt & 1;
        unsigned phase = (cnt >> 1) & 1;
        mbar_wait(wmbar + s * 8, phase);

        int row = c * ROWS_W + lane;
        const float4* xr = ws + s * F4_W + lane * 25;
        float s0 = 0.0f, s1 = 0.0f;
        #pragma unroll
        for (int i = 0; i < 25; i++) {
            float4 v  = xr[i];
            float4 m0 = sM4[i];
            float4 m1 = sM4[25 + i];
            s0 = fmaf(v.x, m0.x, s0); s0 = fmaf(v.y, m0.y, s0);
            s0 = fmaf(v.z, m0.z, s0); s0 = fmaf(v.w, m0.w, s0);
            s1 = fmaf(v.x, m1.x, s1); s1 = fmaf(v.y, m1.y, s1);
            s1 = fmaf(v.z, m1.z, s1); s1 = fmaf(v.w, m1.w, s1);
        }
        if (row < batch) out[row] = make_float2(s0, s1);
        __syncwarp();                      // whole warp done reading stage s

        int cn = c + STAGES * stride;
        if (cn < nchunks) issue(cn, s);
    }
}

extern "C" void kernel_launch(void* const* d_in, const int* in_sizes, int n_in,
                              void* d_out, int out_size) {
    const float* x        = (const float*)d_in[0];  // [BATCH, 100]
    const float* A_real   = (const float*)d_in[1];  // [2,10,10,100]
    const float* A_imag   = (const float*)d_in[2];  // [2,10,10,100]
    const float* psi_real = (const float*)d_in[3];  // [10]
    const float* psi_imag = (const float*)d_in[4];  // [10]

    int batch   = in_sizes[0] / 100;
    int nchunks = (batch + ROWS_W - 1) / ROWS_W;

    static bool attr_done = false;
    if (!attr_done) {
        cudaFuncSetAttribute(fused_kernel,
                             cudaFuncAttributeMaxDynamicSharedMemorySize, SMEM_BYTES);
        attr_done = true;
    }

    fused_kernel<<<148, BLOCK_T, SMEM_BYTES>>>(x, A_real, A_imag,
                                               psi_real, psi_imag,
                                               reinterpret_cast<float2*>(d_out),
                                               batch, nchunks);
}